// round 3
// baseline (speedup 1.0000x reference)
#include <cuda_runtime.h>
#include <math.h>

#define NN 50000
#define EE 800000
#define U  128
#define ED 64
#define NDEPTH 4

// ---------------- scratch (static device memory; no runtime allocation) ----
__device__ float g_h[NN * U];            // current node features
__device__ float g_hn[NN * U];           // h @ Wn for current direction
__device__ float g_gat[NN * U];          // f + bk accumulator
__device__ float g_tmp[NN * U];          // after Wo gemm + residual
__device__ float g_repr[NDEPTH * NN * U]; // per-depth representations
__device__ float g_score[EE * 8];        // per-edge per-head score -> ex -> alpha
__device__ float g_maxv[NN * 8];         // segment max per (node, head)
__device__ float g_den[NN * 8];          // segment sum per (node, head)

// ---------------- helpers ---------------------------------------------------
__device__ __forceinline__ void atomicMaxF(float* addr, float v) {
    if (v >= 0.0f) atomicMax((int*)addr, __float_as_int(v));
    else           atomicMin((unsigned int*)addr, __float_as_uint(v));
}

// ---------------- init kernels ----------------------------------------------
__global__ void k_copy_h(const float* __restrict__ nf) {
    int i = blockIdx.x * 256 + threadIdx.x;
    if (i < NN * U) g_h[i] = nf[i];
}
__global__ void k_clear_gat() {
    int i = blockIdx.x * 256 + threadIdx.x;
    if (i < NN * U) g_gat[i] = 0.0f;
}
__global__ void k_init_maxden() {
    int i = blockIdx.x * 256 + threadIdx.x;
    if (i < NN * 8) { g_maxv[i] = __int_as_float(0xff800000); g_den[i] = 0.0f; }
}

// ---------------- GEMM: C[M,128] = A[M,128] @ B[128,128] (+bias)(+resid) ----
__global__ __launch_bounds__(128) void k_gemm128(
    const float* __restrict__ A, const float* __restrict__ B,
    const float* __restrict__ bias, const float* __restrict__ resid,
    float* __restrict__ C, int M)
{
    extern __shared__ float Bs[];          // 128*128 floats = 64KB (dynamic)
    __shared__ float As[U];
    int tid = threadIdx.x;
    for (int i = tid; i < U * U; i += 128) Bs[i] = B[i];
    __syncthreads();
    int row0 = blockIdx.x * 32;
    for (int r = 0; r < 32; r++) {
        int row = row0 + r;
        bool ok = row < M;                 // uniform across block
        if (ok) As[tid] = A[row * U + tid];
        __syncthreads();
        if (ok) {
            float acc = bias ? bias[tid] : 0.0f;
            #pragma unroll
            for (int k = 0; k < U; k++) acc += As[k] * Bs[k * U + tid];
            if (resid) acc += resid[row * U + tid];
            C[row * U + tid] = acc;
        }
        __syncthreads();
    }
}

// ---------------- edge score: ee on-the-fly + leakyrelu + att dot + segmax --
__global__ __launch_bounds__(128) void k_edge_score(
    const float* __restrict__ ef, const int* __restrict__ idx,
    const float* __restrict__ We, const float* __restrict__ bb,
    const float* __restrict__ att)
{
    __shared__ float We_s[ED * U];         // 32KB
    __shared__ float b_s[U], att_s[U], e_s[ED];
    int tid = threadIdx.x;
    for (int i = tid; i < ED * U; i += 128) We_s[i] = We[i];
    b_s[tid] = bb[tid];
    att_s[tid] = att[tid];
    __syncthreads();
    int e0 = blockIdx.x * 256;
    for (int e = e0; e < e0 + 256; e++) {
        int tgt = idx[2 * e];
        int src = idx[2 * e + 1];
        if (tid < ED) e_s[tid] = ef[e * ED + tid];
        __syncthreads();
        float acc = b_s[tid];
        #pragma unroll
        for (int k = 0; k < ED; k++) acc += e_s[k] * We_s[k * U + tid];
        float s = g_hn[src * U + tid] + g_hn[tgt * U + tid] + acc;
        s = s > 0.0f ? s : 0.2f * s;       // leaky_relu 0.2
        float p = s * att_s[tid];
        #pragma unroll
        for (int off = 8; off; off >>= 1) p += __shfl_xor_sync(0xffffffffu, p, off);
        if ((tid & 15) == 0) {
            int hh = tid >> 4;
            g_score[e * 8 + hh] = p;
            atomicMaxF(&g_maxv[tgt * 8 + hh], p);
        }
        __syncthreads();
    }
}

// ---------------- exp + denominator ----------------------------------------
__global__ void k_edge_exp(const int* __restrict__ idx) {
    int i = blockIdx.x * 256 + threadIdx.x;   // i < EE*8 exactly
    int e = i >> 3, hh = i & 7;
    int tgt = idx[2 * e];
    float ex = __expf(g_score[i] - g_maxv[tgt * 8 + hh]);
    g_score[i] = ex;
    atomicAdd(&g_den[tgt * 8 + hh], ex);
}

// ---------------- normalize to alpha ----------------------------------------
__global__ void k_edge_alpha(const int* __restrict__ idx) {
    int i = blockIdx.x * 256 + threadIdx.x;   // i < EE*8
    int e = i >> 3, hh = i & 7;
    int tgt = idx[2 * e];
    g_score[i] = g_score[i] / (g_den[tgt * 8 + hh] + 1e-9f);
}

// ---------------- scatter: out[tgt] += alpha * hn[src] ----------------------
__global__ void k_edge_scatter(const int* __restrict__ idx) {
    int i = blockIdx.x * 256 + threadIdx.x;   // i < EE*128
    int e = i >> 7, t = i & 127;
    int tgt = idx[2 * e];
    int src = idx[2 * e + 1];
    int hh = t >> 4;
    float v = g_score[e * 8 + hh] * g_hn[src * U + t];
    atomicAdd(&g_gat[tgt * U + t], v);
}

// ---------------- RMS norm --------------------------------------------------
__global__ __launch_bounds__(128) void k_rms(
    const float* __restrict__ X, const float* __restrict__ gm, float* __restrict__ Y)
{
    __shared__ float red[4];
    int n = blockIdx.x, tid = threadIdx.x;
    float v = X[n * U + tid];
    float s = v * v;
    #pragma unroll
    for (int off = 16; off; off >>= 1) s += __shfl_xor_sync(0xffffffffu, s, off);
    if ((tid & 31) == 0) red[tid >> 5] = s;
    __syncthreads();
    float tot = red[0] + red[1] + red[2] + red[3];
    float r = rsqrtf(tot * (1.0f / U) + 1e-6f);
    Y[n * U + tid] = v * r * gm[tid];
}

// ---------------- final fusion: tanh GEMM + depth softmax + rms -------------
__global__ __launch_bounds__(128) void k_fusion(
    const float* __restrict__ moW, const float* __restrict__ mob,
    const float* __restrict__ moww, const float* __restrict__ mowb,
    const float* __restrict__ fg, float* __restrict__ out, int M)
{
    extern __shared__ float Ws[];          // 128*128 = 64KB
    __shared__ float rs[NDEPTH][U];
    __shared__ float mob_s[U], mw_s[U], fg_s[U];
    __shared__ float red[4][NDEPTH];
    __shared__ float red2[4];
    int tid = threadIdx.x;
    for (int i = tid; i < U * U; i += 128) Ws[i] = moW[i];
    mob_s[tid] = mob[tid];
    mw_s[tid] = moww[tid];
    fg_s[tid] = fg[tid];
    float mwb = mowb[0];
    __syncthreads();

    int n0 = blockIdx.x * 32;
    for (int j = 0; j < 32; j++) {
        int n = n0 + j;
        bool ok = n < M;                   // uniform per block
        float fused = 0.0f;
        if (ok) {
            #pragma unroll
            for (int d = 0; d < NDEPTH; d++)
                rs[d][tid] = g_repr[d * (NN * U) + n * U + tid];
        }
        __syncthreads();
        if (ok) {
            float z[NDEPTH];
            #pragma unroll
            for (int d = 0; d < NDEPTH; d++) {
                float acc = mob_s[tid];
                #pragma unroll
                for (int k = 0; k < U; k++) acc += rs[d][k] * Ws[k * U + tid];
                z[d] = tanhf(acc);
            }
            #pragma unroll
            for (int d = 0; d < NDEPTH; d++) {
                float val = z[d] * mw_s[tid];
                #pragma unroll
                for (int off = 16; off; off >>= 1)
                    val += __shfl_xor_sync(0xffffffffu, val, off);
                if ((tid & 31) == 0) red[tid >> 5][d] = val;
            }
        }
        __syncthreads();
        if (ok) {
            float sd[NDEPTH], m = -1e30f;
            #pragma unroll
            for (int d = 0; d < NDEPTH; d++) {
                sd[d] = red[0][d] + red[1][d] + red[2][d] + red[3][d] + mwb;
                m = fmaxf(m, sd[d]);
            }
            float w[NDEPTH], wsum = 0.0f;
            #pragma unroll
            for (int d = 0; d < NDEPTH; d++) { w[d] = __expf(sd[d] - m); wsum += w[d]; }
            float inv = 1.0f / wsum;
            #pragma unroll
            for (int d = 0; d < NDEPTH; d++) fused += (w[d] * inv) * rs[d][tid];
            float s2 = fused * fused;
            #pragma unroll
            for (int off = 16; off; off >>= 1)
                s2 += __shfl_xor_sync(0xffffffffu, s2, off);
            if ((tid & 31) == 0) red2[tid >> 5] = s2;
        }
        __syncthreads();
        if (ok) {
            float tot = red2[0] + red2[1] + red2[2] + red2[3];
            out[n * U + tid] = fused * rsqrtf(tot * (1.0f / U) + 1e-6f) * fg_s[tid];
        }
        __syncthreads();
    }
}

// ---------------- host driver ----------------------------------------------
extern "C" void kernel_launch(void* const* d_in, const int* in_sizes, int n_in,
                              void* d_out, int out_size)
{
    const float* node_features = (const float*)d_in[0];
    const float* edge_features = (const float*)d_in[1];
    const int*   ei_fwd        = (const int*)d_in[2];
    const int*   ei_bwd        = (const int*)d_in[3];
    const float* Wn_f  = (const float*)d_in[4];
    const float* We_f  = (const float*)d_in[5];
    const float* b_f   = (const float*)d_in[6];
    const float* att_f = (const float*)d_in[7];
    const float* Wn_b  = (const float*)d_in[8];
    const float* We_b  = (const float*)d_in[9];
    const float* b_b   = (const float*)d_in[10];
    const float* att_b = (const float*)d_in[11];
    const float* Wo    = (const float*)d_in[12];
    const float* bo    = (const float*)d_in[13];
    const float* gamma = (const float*)d_in[14];
    const float* mo_W  = (const float*)d_in[15];
    const float* mo_b  = (const float*)d_in[16];
    const float* mow_W = (const float*)d_in[17];
    const float* mow_b = (const float*)d_in[18];
    const float* final_gamma = (const float*)d_in[19];

    float *p_h, *p_hn, *p_gat, *p_tmp, *p_repr;
    cudaGetSymbolAddress((void**)&p_h,    g_h);
    cudaGetSymbolAddress((void**)&p_hn,   g_hn);
    cudaGetSymbolAddress((void**)&p_gat,  g_gat);
    cudaGetSymbolAddress((void**)&p_tmp,  g_tmp);
    cudaGetSymbolAddress((void**)&p_repr, g_repr);

    cudaFuncSetAttribute(k_gemm128, cudaFuncAttributeMaxDynamicSharedMemorySize, 65536);
    cudaFuncSetAttribute(k_fusion,  cudaFuncAttributeMaxDynamicSharedMemorySize, 65536);

    const int GEMM_GRID = (NN + 31) / 32;          // 1563
    const int EDGE_GRID = EE / 256;                // 3125
    const int EH_GRID   = (EE * 8) / 256;          // 25000
    const int SCAT_GRID = (EE * 128) / 256;        // 400000

    k_copy_h<<<(NN * U + 255) / 256, 256>>>(node_features);

    for (int i = 0; i < NDEPTH; i++) {
        k_clear_gat<<<(NN * U + 255) / 256, 256>>>();
        for (int dir = 0; dir < 2; dir++) {
            const float* Wn  = (dir ? Wn_b  : Wn_f)  + i * U * U;
            const float* We  = (dir ? We_b  : We_f)  + i * ED * U;
            const float* bb  = (dir ? b_b   : b_f)   + i * U;
            const float* att = (dir ? att_b : att_f) + i * U;
            const int*   idx = dir ? ei_bwd : ei_fwd;

            k_gemm128<<<GEMM_GRID, 128, 65536>>>(p_h, Wn, nullptr, nullptr, p_hn, NN);
            k_init_maxden<<<(NN * 8 + 255) / 256, 256>>>();
            k_edge_score<<<EDGE_GRID, 128>>>(edge_features, idx, We, bb, att);
            k_edge_exp<<<EH_GRID, 256>>>(idx);
            k_edge_alpha<<<EH_GRID, 256>>>(idx);
            k_edge_scatter<<<SCAT_GRID, 256>>>(idx);
        }
        // out = (f+bk) @ Wo + bo + h
        k_gemm128<<<GEMM_GRID, 128, 65536>>>(p_gat, Wo + i * U * U, bo + i * U, p_h,
                                             p_tmp, NN);
        // repr[i] = rms(out, gamma[i])
        k_rms<<<NN, 128>>>(p_tmp, gamma + i * U, p_repr + i * NN * U);
        // h = rms(repr[i], final_gamma)  (only needed for i < DEPTH-1)
        if (i < NDEPTH - 1)
            k_rms<<<NN, 128>>>(p_repr + i * NN * U, final_gamma, p_h);
    }

    k_fusion<<<GEMM_GRID, 128, 65536>>>(mo_W, mo_b, mow_W, mow_b, final_gamma,
                                        (float*)d_out, NN);
}

// round 4
// speedup vs baseline: 2.5133x; 2.5133x over previous
#include <cuda_runtime.h>
#include <math.h>

#define NN 50000
#define EE 800000
#define U  128
#define ED 64
#define NDEPTH 4
#define NBLK 196   /* ceil(NN/256) */

// ---------------- scratch (static device memory) ---------------------------
__device__ float g_h[NN * U];
__device__ float g_hn[NN * U];
__device__ float g_gat[NN * U];
__device__ float g_tmp[NN * U];
__device__ float g_repr[NDEPTH * NN * U];
__device__ float g_z[NDEPTH * NN * U];
__device__ float g_score[EE * 8];          // raw per-edge per-head scores (CSR order)
__device__ int g_degF[NN], g_degB[NN], g_curF[NN], g_curB[NN];
__device__ int g_rpF[NN + 1], g_rpB[NN + 1];
__device__ int g_srcF[EE], g_srcB[EE], g_posF[EE], g_posB[EE];
__device__ int g_bsum[256];

// ---------------- packed f32x2 helpers --------------------------------------
__device__ __forceinline__ unsigned long long pk(float x, float y) {
    unsigned long long r;
    asm("mov.b64 %0,{%1,%2};" : "=l"(r) : "f"(x), "f"(y));
    return r;
}
__device__ __forceinline__ void fma2(unsigned long long& d, unsigned long long a,
                                     unsigned long long b) {
    asm("fma.rn.f32x2 %0,%1,%2,%0;" : "+l"(d) : "l"(a), "l"(b));
}
__device__ __forceinline__ float2 upk(unsigned long long v) {
    float2 f;
    asm("mov.b64 {%0,%1},%2;" : "=f"(f.x), "=f"(f.y) : "l"(v));
    return f;
}

// ---------------- CSR build --------------------------------------------------
__global__ void k_zero_counts() {
    int i = blockIdx.x * 256 + threadIdx.x;
    if (i < NN) { g_degF[i] = 0; g_degB[i] = 0; g_curF[i] = 0; g_curB[i] = 0; }
}
__global__ void k_count(const int2* __restrict__ ei) {
    int e = blockIdx.x * 256 + threadIdx.x;   // e < EE exactly
    int2 t = ei[e];
    atomicAdd(&g_degF[t.x], 1);
    atomicAdd(&g_degB[t.y], 1);
}
__device__ __forceinline__ int blockscan_incl(int v, int* shw) {
    int lane = threadIdx.x & 31, wid = threadIdx.x >> 5;
    #pragma unroll
    for (int o = 1; o < 32; o <<= 1) {
        int t = __shfl_up_sync(0xffffffffu, v, o);
        if (lane >= o) v += t;
    }
    if (lane == 31) shw[wid] = v;
    __syncthreads();
    if (wid == 0) {
        int s = (lane < 8) ? shw[lane] : 0;
        #pragma unroll
        for (int o = 1; o < 8; o <<= 1) {
            int t = __shfl_up_sync(0xffffffffu, s, o);
            if (lane >= o) s += t;
        }
        if (lane < 8) shw[lane] = s;
    }
    __syncthreads();
    if (wid) v += shw[wid - 1];
    return v;
}
__global__ void k_blocksum(const int* __restrict__ deg, int* __restrict__ bsum) {
    __shared__ int sh[256];
    int tid = threadIdx.x;
    int i = blockIdx.x * 256 + tid;
    sh[tid] = (i < NN) ? deg[i] : 0;
    __syncthreads();
    for (int s = 128; s; s >>= 1) { if (tid < s) sh[tid] += sh[tid + s]; __syncthreads(); }
    if (tid == 0) bsum[blockIdx.x] = sh[0];
}
__global__ void k_scanbsums(int* __restrict__ bsum, int nb) {
    __shared__ int shw[32];
    int tid = threadIdx.x;
    int v = (tid < nb) ? bsum[tid] : 0;
    int incl = blockscan_incl(v, shw);
    if (tid < nb) bsum[tid] = incl - v;
}
__global__ void k_scanfinal(const int* __restrict__ deg, const int* __restrict__ bsum,
                            int* __restrict__ rowptr) {
    __shared__ int shw[32];
    int tid = threadIdx.x;
    int i = blockIdx.x * 256 + tid;
    int v = (i < NN) ? deg[i] : 0;
    int incl = blockscan_incl(v, shw);
    int base = bsum[blockIdx.x];
    if (i < NN) rowptr[i] = incl - v + base;
    if (i == NN - 1) rowptr[NN] = incl + base;
}
__global__ void k_fill(const int2* __restrict__ ei) {
    int e = blockIdx.x * 256 + threadIdx.x;
    int2 t = ei[e];
    int pf = g_rpF[t.x] + atomicAdd(&g_curF[t.x], 1);
    g_srcF[pf] = t.y; g_posF[e] = pf;
    int pb = g_rpB[t.y] + atomicAdd(&g_curB[t.y], 1);
    g_srcB[pb] = t.x; g_posB[e] = pb;
}

// ---------------- GEMM: C[M,128] = A[M,128]@B[128,128] (+bias)(+resid)(tanh) -
__global__ __launch_bounds__(128) void k_gemm128(
    const float* __restrict__ A, const float* __restrict__ B,
    const float* __restrict__ bias, const float* __restrict__ resid,
    float* __restrict__ C, int M, int mode)
{
    extern __shared__ float sm[];
    float* Bs = sm;                 // 128*128
    float* As = sm + U * U;         // 32*129 (padded)
    int tid = threadIdx.x;
    for (int i = tid; i < U * U; i += 128) Bs[i] = B[i];
    int row0 = blockIdx.x * 32;
    for (int i = tid; i < 32 * U; i += 128) {
        int r = i >> 7, c = i & 127;
        int rr = row0 + r;
        As[r * 129 + c] = (rr < M) ? A[rr * U + c] : 0.0f;
    }
    __syncthreads();
    int cg = tid & 15, rg = tid >> 4;
    unsigned long long acc[4][4];
    #pragma unroll
    for (int r = 0; r < 4; r++)
        #pragma unroll
        for (int j = 0; j < 4; j++) acc[r][j] = 0ull;
    const float* Bp = Bs + cg * 8;
    const float* Ap = As + rg * 4 * 129;
    #pragma unroll 8
    for (int k = 0; k < U; k++) {
        float4 w0 = *(const float4*)(Bp + k * U);
        float4 w1 = *(const float4*)(Bp + k * U + 4);
        unsigned long long b0 = pk(w0.x, w0.y), b1 = pk(w0.z, w0.w);
        unsigned long long b2 = pk(w1.x, w1.y), b3 = pk(w1.z, w1.w);
        #pragma unroll
        for (int r = 0; r < 4; r++) {
            float a = Ap[r * 129 + k];
            unsigned long long aa = pk(a, a);
            fma2(acc[r][0], aa, b0);
            fma2(acc[r][1], aa, b1);
            fma2(acc[r][2], aa, b2);
            fma2(acc[r][3], aa, b3);
        }
    }
    float bv[8];
    #pragma unroll
    for (int j = 0; j < 8; j++) bv[j] = bias ? bias[cg * 8 + j] : 0.0f;
    #pragma unroll
    for (int r = 0; r < 4; r++) {
        int row = row0 + rg * 4 + r;
        if (row >= M) continue;
        float o[8];
        #pragma unroll
        for (int j = 0; j < 4; j++) {
            float2 f = upk(acc[r][j]);
            o[2 * j] = f.x + bv[2 * j];
            o[2 * j + 1] = f.y + bv[2 * j + 1];
        }
        if (resid) {
            float4 r0v = *(const float4*)(resid + row * U + cg * 8);
            float4 r1v = *(const float4*)(resid + row * U + cg * 8 + 4);
            o[0] += r0v.x; o[1] += r0v.y; o[2] += r0v.z; o[3] += r0v.w;
            o[4] += r1v.x; o[5] += r1v.y; o[6] += r1v.z; o[7] += r1v.w;
        }
        if (mode & 1) {
            #pragma unroll
            for (int j = 0; j < 8; j++) o[j] = tanhf(o[j]);
        }
        float4 s0 = {o[0], o[1], o[2], o[3]};
        float4 s1 = {o[4], o[5], o[6], o[7]};
        ((float4*)(C + row * U + cg * 8))[0] = s0;
        ((float4*)(C + row * U + cg * 8))[1] = s1;
    }
}

// ---------------- edge score: warp-per-edge, f32x2, writes CSR-permuted -----
__global__ __launch_bounds__(256) void k_edge_score(
    const float* __restrict__ ef, const int2* __restrict__ ei,
    const float* __restrict__ We, const float* __restrict__ bb,
    const float* __restrict__ att, const int* __restrict__ posArr)
{
    __shared__ alignas(16) float We_s[ED * U];   // 32KB
    __shared__ float b_s[U], att_s[U];
    int tid = threadIdx.x;
    for (int i = tid; i < ED * U; i += 256) We_s[i] = We[i];
    if (tid < U) { b_s[tid] = bb[tid]; att_s[tid] = att[tid]; }
    __syncthreads();
    int wid = tid >> 5, lane = tid & 31;
    #pragma unroll 1
    for (int it = 0; it < 16; it++) {
        int e = blockIdx.x * 128 + it * 8 + wid;   // grid 6250 -> covers EE exactly
        int2 ts = ei[e];
        int tgt = ts.x, src = ts.y;
        float2 ev = ((const float2*)ef)[e * 32 + lane];
        float4 hs = *(const float4*)(g_hn + src * U + lane * 4);
        float4 ht = *(const float4*)(g_hn + tgt * U + lane * 4);
        unsigned long long acc01 = pk(b_s[lane * 4], b_s[lane * 4 + 1]);
        unsigned long long acc23 = pk(b_s[lane * 4 + 2], b_s[lane * 4 + 3]);
        #pragma unroll
        for (int k = 0; k < ED; k++) {
            float a = __shfl_sync(0xffffffffu, (k & 1) ? ev.y : ev.x, k >> 1);
            float4 w = *(const float4*)&We_s[k * U + lane * 4];
            unsigned long long aa = pk(a, a);
            fma2(acc01, aa, pk(w.x, w.y));
            fma2(acc23, aa, pk(w.z, w.w));
        }
        float2 f01 = upk(acc01), f23 = upk(acc23);
        float s0 = hs.x + ht.x + f01.x;
        float s1 = hs.y + ht.y + f01.y;
        float s2 = hs.z + ht.z + f23.x;
        float s3 = hs.w + ht.w + f23.y;
        s0 = s0 > 0.0f ? s0 : 0.2f * s0;
        s1 = s1 > 0.0f ? s1 : 0.2f * s1;
        s2 = s2 > 0.0f ? s2 : 0.2f * s2;
        s3 = s3 > 0.0f ? s3 : 0.2f * s3;
        float p = s0 * att_s[lane * 4] + s1 * att_s[lane * 4 + 1]
                + s2 * att_s[lane * 4 + 2] + s3 * att_s[lane * 4 + 3];
        p += __shfl_xor_sync(0xffffffffu, p, 1);
        p += __shfl_xor_sync(0xffffffffu, p, 2);
        if ((lane & 3) == 0) {
            int pos = posArr[e];
            g_score[pos * 8 + (lane >> 2)] = p;
        }
    }
}

// ---------------- segment softmax + weighted aggregation (warp per node) ----
__device__ __forceinline__ float sel8(const float a[8], int h) {
    float r = a[0];
    r = (h == 1) ? a[1] : r; r = (h == 2) ? a[2] : r; r = (h == 3) ? a[3] : r;
    r = (h == 4) ? a[4] : r; r = (h == 5) ? a[5] : r; r = (h == 6) ? a[6] : r;
    r = (h == 7) ? a[7] : r;
    return r;
}
__global__ __launch_bounds__(256) void k_aggregate(
    const int* __restrict__ rowptr, const int* __restrict__ srcarr, int accumulate)
{
    int n = blockIdx.x * 8 + (threadIdx.x >> 5);
    int lane = threadIdx.x & 31;
    if (n >= NN) return;
    int r0 = rowptr[n], r1 = rowptr[n + 1];
    int h4 = lane >> 2;
    // pass 1: per-head max
    float m[8];
    #pragma unroll
    for (int h = 0; h < 8; h++) m[h] = -3.0e38f;
    for (int i = r0 + lane; i < r1; i += 32) {
        const float4* sp = (const float4*)(g_score + i * 8);
        float4 a = sp[0], b = sp[1];
        m[0] = fmaxf(m[0], a.x); m[1] = fmaxf(m[1], a.y);
        m[2] = fmaxf(m[2], a.z); m[3] = fmaxf(m[3], a.w);
        m[4] = fmaxf(m[4], b.x); m[5] = fmaxf(m[5], b.y);
        m[6] = fmaxf(m[6], b.z); m[7] = fmaxf(m[7], b.w);
    }
    #pragma unroll
    for (int off = 16; off; off >>= 1)
        #pragma unroll
        for (int h = 0; h < 8; h++)
            m[h] = fmaxf(m[h], __shfl_xor_sync(0xffffffffu, m[h], off));
    // pass 2: denominator
    float den[8];
    #pragma unroll
    for (int h = 0; h < 8; h++) den[h] = 0.0f;
    for (int i = r0 + lane; i < r1; i += 32) {
        const float4* sp = (const float4*)(g_score + i * 8);
        float4 a = sp[0], b = sp[1];
        den[0] += __expf(a.x - m[0]); den[1] += __expf(a.y - m[1]);
        den[2] += __expf(a.z - m[2]); den[3] += __expf(a.w - m[3]);
        den[4] += __expf(b.x - m[4]); den[5] += __expf(b.y - m[5]);
        den[6] += __expf(b.z - m[6]); den[7] += __expf(b.w - m[7]);
    }
    #pragma unroll
    for (int off = 16; off; off >>= 1)
        #pragma unroll
        for (int h = 0; h < 8; h++)
            den[h] += __shfl_xor_sync(0xffffffffu, den[h], off);
    float myinv = 1.0f / (sel8(den, h4) + 1e-9f);
    float mh = sel8(m, h4);
    // pass 3: out[n] = sum_e alpha_eh * hn[src_e]
    float4 acc = {0.0f, 0.0f, 0.0f, 0.0f};
    for (int i = r0; i < r1; i++) {
        int src = srcarr[i];
        float sc = g_score[i * 8 + h4];
        float al = __expf(sc - mh) * myinv;
        float4 hv = *(const float4*)(g_hn + src * U + lane * 4);
        acc.x += al * hv.x; acc.y += al * hv.y;
        acc.z += al * hv.z; acc.w += al * hv.w;
    }
    float* outp = g_gat + n * U + lane * 4;
    if (accumulate) {
        float4 o = *(float4*)outp;
        acc.x += o.x; acc.y += o.y; acc.z += o.z; acc.w += o.w;
    }
    *(float4*)outp = acc;
}

// ---------------- dual RMS: repr = rms(x,gamma); h = rms(repr, fg) ----------
__global__ __launch_bounds__(128) void k_rms_dual(
    const float* __restrict__ X, const float* __restrict__ gm,
    const float* __restrict__ fg, float* __restrict__ Yrep, float* __restrict__ Yh)
{
    __shared__ float red[4];
    int n = blockIdx.x, tid = threadIdx.x;
    float v = X[n * U + tid];
    float s = v * v;
    #pragma unroll
    for (int off = 16; off; off >>= 1) s += __shfl_xor_sync(0xffffffffu, s, off);
    if ((tid & 31) == 0) red[tid >> 5] = s;
    __syncthreads();
    float tot = red[0] + red[1] + red[2] + red[3];
    float r1 = rsqrtf(tot * (1.0f / U) + 1e-6f);
    float rep = v * r1 * gm[tid];
    Yrep[n * U + tid] = rep;
    if (Yh) {
        __syncthreads();
        float s2 = rep * rep;
        #pragma unroll
        for (int off = 16; off; off >>= 1) s2 += __shfl_xor_sync(0xffffffffu, s2, off);
        if ((tid & 31) == 0) red[tid >> 5] = s2;
        __syncthreads();
        float tot2 = red[0] + red[1] + red[2] + red[3];
        float r2 = rsqrtf(tot2 * (1.0f / U) + 1e-6f);
        Yh[n * U + tid] = rep * r2 * fg[tid];
    }
}

// ---------------- depth-attention fusion (z precomputed via tanh GEMM) ------
__global__ __launch_bounds__(128) void k_fuse2(
    const float* __restrict__ mw, const float* __restrict__ mwb,
    const float* __restrict__ fg, float* __restrict__ out)
{
    __shared__ float red[4][NDEPTH];
    __shared__ float red2[4];
    int n = blockIdx.x, tid = threadIdx.x;
    float mwv = mw[tid];
    float z[NDEPTH], rep[NDEPTH];
    #pragma unroll
    for (int d = 0; d < NDEPTH; d++) {
        z[d] = g_z[d * (NN * U) + n * U + tid];
        rep[d] = g_repr[d * (NN * U) + n * U + tid];
    }
    #pragma unroll
    for (int d = 0; d < NDEPTH; d++) {
        float val = z[d] * mwv;
        #pragma unroll
        for (int off = 16; off; off >>= 1) val += __shfl_xor_sync(0xffffffffu, val, off);
        if ((tid & 31) == 0) red[tid >> 5][d] = val;
    }
    __syncthreads();
    float b0 = mwb[0];
    float sd[NDEPTH], mx = -1e30f;
    #pragma unroll
    for (int d = 0; d < NDEPTH; d++) {
        sd[d] = red[0][d] + red[1][d] + red[2][d] + red[3][d] + b0;
        mx = fmaxf(mx, sd[d]);
    }
    float w[NDEPTH], wsum = 0.0f;
    #pragma unroll
    for (int d = 0; d < NDEPTH; d++) { w[d] = __expf(sd[d] - mx); wsum += w[d]; }
    float inv = 1.0f / wsum;
    float fused = 0.0f;
    #pragma unroll
    for (int d = 0; d < NDEPTH; d++) fused += (w[d] * inv) * rep[d];
    float s2 = fused * fused;
    #pragma unroll
    for (int off = 16; off; off >>= 1) s2 += __shfl_xor_sync(0xffffffffu, s2, off);
    if ((tid & 31) == 0) red2[tid >> 5] = s2;
    __syncthreads();
    float tot = red2[0] + red2[1] + red2[2] + red2[3];
    out[n * U + tid] = fused * rsqrtf(tot * (1.0f / U) + 1e-6f) * fg[tid];
}

// ---------------- host driver ----------------------------------------------
extern "C" void kernel_launch(void* const* d_in, const int* in_sizes, int n_in,
                              void* d_out, int out_size)
{
    const float* node_features = (const float*)d_in[0];
    const float* edge_features = (const float*)d_in[1];
    const int*   ei_fwd        = (const int*)d_in[2];
    const int*   ei_bwd        = (const int*)d_in[3];
    const float* Wn_f  = (const float*)d_in[4];
    const float* We_f  = (const float*)d_in[5];
    const float* b_f   = (const float*)d_in[6];
    const float* att_f = (const float*)d_in[7];
    const float* Wn_b  = (const float*)d_in[8];
    const float* We_b  = (const float*)d_in[9];
    const float* b_b   = (const float*)d_in[10];
    const float* att_b = (const float*)d_in[11];
    const float* Wo    = (const float*)d_in[12];
    const float* bo    = (const float*)d_in[13];
    const float* gamma = (const float*)d_in[14];
    const float* mo_W  = (const float*)d_in[15];
    const float* mo_b  = (const float*)d_in[16];
    const float* mow_W = (const float*)d_in[17];
    const float* mow_b = (const float*)d_in[18];
    const float* final_gamma = (const float*)d_in[19];

    float *p_h, *p_hn, *p_gat, *p_tmp, *p_repr, *p_z;
    int *p_degF, *p_degB, *p_rpF, *p_rpB, *p_srcF, *p_srcB, *p_posF, *p_posB, *p_bsum;
    cudaGetSymbolAddress((void**)&p_h,    g_h);
    cudaGetSymbolAddress((void**)&p_hn,   g_hn);
    cudaGetSymbolAddress((void**)&p_gat,  g_gat);
    cudaGetSymbolAddress((void**)&p_tmp,  g_tmp);
    cudaGetSymbolAddress((void**)&p_repr, g_repr);
    cudaGetSymbolAddress((void**)&p_z,    g_z);
    cudaGetSymbolAddress((void**)&p_degF, g_degF);
    cudaGetSymbolAddress((void**)&p_degB, g_degB);
    cudaGetSymbolAddress((void**)&p_rpF,  g_rpF);
    cudaGetSymbolAddress((void**)&p_rpB,  g_rpB);
    cudaGetSymbolAddress((void**)&p_srcF, g_srcF);
    cudaGetSymbolAddress((void**)&p_srcB, g_srcB);
    cudaGetSymbolAddress((void**)&p_posF, g_posF);
    cudaGetSymbolAddress((void**)&p_posB, g_posB);
    cudaGetSymbolAddress((void**)&p_bsum, g_bsum);

    const int GEMM_SMEM = (U * U + 32 * 129) * (int)sizeof(float);  // 82048
    cudaFuncSetAttribute(k_gemm128, cudaFuncAttributeMaxDynamicSharedMemorySize, GEMM_SMEM);

    const int GEMM_GRID = (NN + 31) / 32;   // 1563
    const int ES_GRID   = EE / 128;         // 6250
    const int AGG_GRID  = (NN + 7) / 8;     // 6250

    // --- CSR build (once per call; shared across all depths/dirs) ---
    k_zero_counts<<<NBLK, 256>>>();
    k_count<<<EE / 256, 256>>>((const int2*)ei_fwd);
    k_blocksum<<<NBLK, 256>>>(p_degF, p_bsum);
    k_scanbsums<<<1, 256>>>(p_bsum, NBLK);
    k_scanfinal<<<NBLK, 256>>>(p_degF, p_bsum, p_rpF);
    k_blocksum<<<NBLK, 256>>>(p_degB, p_bsum);
    k_scanbsums<<<1, 256>>>(p_bsum, NBLK);
    k_scanfinal<<<NBLK, 256>>>(p_degB, p_bsum, p_rpB);
    k_fill<<<EE / 256, 256>>>((const int2*)ei_fwd);

    const float* hcur = node_features;
    for (int i = 0; i < NDEPTH; i++) {
        // forward direction
        k_gemm128<<<GEMM_GRID, 128, GEMM_SMEM>>>(hcur, Wn_f + i * U * U,
                                                 nullptr, nullptr, p_hn, NN, 0);
        k_edge_score<<<ES_GRID, 256>>>(edge_features, (const int2*)ei_fwd,
                                       We_f + i * ED * U, b_f + i * U,
                                       att_f + i * U, p_posF);
        k_aggregate<<<AGG_GRID, 256>>>(p_rpF, p_srcF, 0);
        // backward direction
        k_gemm128<<<GEMM_GRID, 128, GEMM_SMEM>>>(hcur, Wn_b + i * U * U,
                                                 nullptr, nullptr, p_hn, NN, 0);
        k_edge_score<<<ES_GRID, 256>>>(edge_features, (const int2*)ei_bwd,
                                       We_b + i * ED * U, b_b + i * U,
                                       att_b + i * U, p_posB);
        k_aggregate<<<AGG_GRID, 256>>>(p_rpB, p_srcB, 1);
        // out = (f+bk) @ Wo + bo + h ; repr = rms(out,gamma); h = rms(repr,fg)
        k_gemm128<<<GEMM_GRID, 128, GEMM_SMEM>>>(p_gat, Wo + i * U * U,
                                                 bo + i * U, hcur, p_tmp, NN, 0);
        k_rms_dual<<<NN, 128>>>(p_tmp, gamma + i * U, final_gamma,
                                p_repr + i * NN * U,
                                (i < NDEPTH - 1) ? p_h : nullptr);
        hcur = p_h;
    }

    // fusion head: z_d = tanh(repr_d @ mo_W + mo_b), then depth softmax + rms
    for (int d = 0; d < NDEPTH; d++)
        k_gemm128<<<GEMM_GRID, 128, GEMM_SMEM>>>(p_repr + d * NN * U, mo_W, mo_b,
                                                 nullptr, p_z + d * NN * U, NN, 1);
    k_fuse2<<<NN, 128>>>(mow_W, mow_b, final_gamma, (float*)d_out);
}